// round 2
// baseline (speedup 1.0000x reference)
#include <cuda_runtime.h>
#include <math.h>

#define T_TOK 512
#define CHUNK 64
#define NCHUNK 8
#define HH 28
#define WW 28
#define CC 4
#define DM 3136
#define DH 512

// ---------------- device scratch (no allocation allowed) ----------------
__device__ __align__(16) float g_nk[T_TOK * DM];
__device__ __align__(16) float g_nv[T_TOK * DM];
__device__ __align__(16) float g_W1[DM * DH];
__device__ __align__(16) float g_W2[DH * DM];
__device__ __align__(16) float g_b1[DH];
__device__ __align__(16) float g_b2[DM];
__device__ __align__(16) float g_H[CHUNK * DH];
__device__ __align__(16) float g_A[CHUNK * DH];
__device__ __align__(16) float g_A2[CHUNK * DH];
__device__ __align__(16) float g_dpred[CHUNK * DM];
__device__ __align__(16) float g_dh[CHUNK * DH];
__device__ __align__(16) float g_fpart[16 * CHUNK * DH];   // fwd split-K partials
__device__ __align__(16) float g_ppart[4 * CHUNK * DM];    // pred split-K partials

// ---------------- math helpers ----------------
__device__ __forceinline__ float gelu_f(float x) {
    const float c = 0.7978845608028654f, a = 0.044715f;
    float u = c * (x + a * x * x * x);
    return 0.5f * x * (1.0f + tanhf(u));
}
__device__ __forceinline__ float dgelu_f(float x) {
    const float c = 0.7978845608028654f, a = 0.044715f;
    float x2 = x * x;
    float u = c * (x + a * x * x2);
    float th = tanhf(u);
    return 0.5f * (1.0f + th) + 0.5f * x * (1.0f - th * th) * c * (1.0f + 3.0f * a * x2);
}

// ---------------- conv3x3 (k & v) + rmsnorm ----------------
__global__ void conv_rms_kernel(const float* __restrict__ x,
                                const float* __restrict__ wk, const float* __restrict__ bk,
                                const float* __restrict__ wv, const float* __restrict__ bv,
                                const float* __restrict__ sk, const float* __restrict__ sv) {
    __shared__ float swk[144], swv[144], sbk[4], sbv[4], ssk[4], ssv[4];
    int tid = threadIdx.x;
    if (tid < 144) { swk[tid] = wk[tid]; swv[tid] = wv[tid]; }
    if (tid < 4) { sbk[tid] = bk[tid]; sbv[tid] = bv[tid]; ssk[tid] = sk[tid]; ssv[tid] = sv[tid]; }
    __syncthreads();
    int idx = blockIdx.x * blockDim.x + tid;
    if (idx >= T_TOK * HH * WW) return;
    int w = idx % WW;
    int h = (idx / WW) % HH;
    int t = idx / (HH * WW);

    float acck[4], accv[4];
#pragma unroll
    for (int o = 0; o < 4; o++) { acck[o] = sbk[o]; accv[o] = sbv[o]; }

    const float* xt = x + t * (CC * HH * WW);
#pragma unroll
    for (int kh = 0; kh < 3; kh++) {
        int hy = h + kh - 1;
        if (hy < 0 || hy >= HH) continue;
#pragma unroll
        for (int kw = 0; kw < 3; kw++) {
            int wx = w + kw - 1;
            if (wx < 0 || wx >= WW) continue;
            int wbase = (kh * 3 + kw) * 16;
#pragma unroll
            for (int ci = 0; ci < 4; ci++) {
                float xv = xt[ci * (HH * WW) + hy * WW + wx];
                const float* wkp = &swk[wbase + ci * 4];
                const float* wvp = &swv[wbase + ci * 4];
#pragma unroll
                for (int o = 0; o < 4; o++) { acck[o] += xv * wkp[o]; accv[o] += xv * wvp[o]; }
            }
        }
    }
    float msk = 0.f, msv = 0.f;
#pragma unroll
    for (int o = 0; o < 4; o++) { msk += acck[o] * acck[o]; msv += accv[o] * accv[o]; }
    float ik = rsqrtf(msk * 0.25f + 1e-6f);
    float iv = rsqrtf(msv * 0.25f + 1e-6f);
    int base = t * DM + (h * WW + w) * CC;
#pragma unroll
    for (int o = 0; o < 4; o++) {
        g_nk[base + o] = acck[o] * ik * ssk[o];
        g_nv[base + o] = accv[o] * iv * ssv[o];
    }
}

// ---------------- copy initial params into scratch ----------------
__global__ void init_kernel(const float* __restrict__ W1, const float* __restrict__ b1,
                            const float* __restrict__ W2, const float* __restrict__ b2) {
    int i = blockIdx.x * blockDim.x + threadIdx.x;
    int stride = gridDim.x * blockDim.x;
    for (int k = i; k < DM * DH; k += stride) { g_W1[k] = W1[k]; g_W2[k] = W2[k]; }
    if (i < DH) g_b1[i] = b1[i];
    if (i < DM) g_b2[i] = b2[i];
}

// ---------------- fwd split-K: partial[seg][m][n] = sum_{k in seg} K[m,k]*W1[k,n] ----------------
// blockDim (16,4): tx -> 16 float4 n-tiles (64 n), ty -> 4 m-subgroups (4 m each -> 16 m)
// grid (8 n-tiles, 4 m-groups, 16 k-segs of 196)
__global__ void fwd_split_kernel(int c) {
    int tx = threadIdx.x, ty = threadIdx.y;
    int n0 = (blockIdx.x * 16 + tx) * 4;
    int m0 = blockIdx.y * 16 + ty * 4;
    int seg = blockIdx.z;
    const float* K = g_nk + (c * CHUNK + m0) * DM;
    float a00=0,a01=0,a02=0,a03=0, a10=0,a11=0,a12=0,a13=0;
    float a20=0,a21=0,a22=0,a23=0, a30=0,a31=0,a32=0,a33=0;
    int k0 = seg * 196;
    const float* Wp = g_W1 + n0;
#pragma unroll 4
    for (int k = k0; k < k0 + 196; k++) {
        float4 w = *reinterpret_cast<const float4*>(Wp + k * DH);
        float x0 = K[k], x1 = K[DM + k], x2 = K[2 * DM + k], x3 = K[3 * DM + k];
        a00 += x0 * w.x; a01 += x0 * w.y; a02 += x0 * w.z; a03 += x0 * w.w;
        a10 += x1 * w.x; a11 += x1 * w.y; a12 += x1 * w.z; a13 += x1 * w.w;
        a20 += x2 * w.x; a21 += x2 * w.y; a22 += x2 * w.z; a23 += x2 * w.w;
        a30 += x3 * w.x; a31 += x3 * w.y; a32 += x3 * w.z; a33 += x3 * w.w;
    }
    float* P = g_fpart + (seg * CHUNK + m0) * DH + n0;
    *reinterpret_cast<float4*>(P)          = make_float4(a00, a01, a02, a03);
    *reinterpret_cast<float4*>(P + DH)     = make_float4(a10, a11, a12, a13);
    *reinterpret_cast<float4*>(P + 2 * DH) = make_float4(a20, a21, a22, a23);
    *reinterpret_cast<float4*>(P + 3 * DH) = make_float4(a30, a31, a32, a33);
}

// ---------------- reduce fwd partials -> H, A (pass selects A vs A2) ----------------
__global__ void reduce1_kernel(int pass) {
    int idx = blockIdx.x * 256 + threadIdx.x;   // 64*512 = 32768 exact
    float s = g_b1[idx & (DH - 1)];
#pragma unroll
    for (int sg = 0; sg < 16; sg++) s += g_fpart[sg * (CHUNK * DH) + idx];
    g_H[idx] = s;
    float a = gelu_f(s);
    if (pass == 0) g_A[idx] = a; else g_A2[idx] = a;
}

// ---------------- pred split-K: partial[seg][m][d] = sum_{j in seg} A[m,j]*W2[j,d] ----------------
// blockDim 64: tx -> float4 d-tiles. grid (13, 8 m-groups of 8, 4 j-segs of 128)
__global__ void pred_split_kernel(int pass) {
    int d4 = blockIdx.x * 64 + threadIdx.x;
    if (d4 >= 784) return;
    int d0 = d4 * 4;
    int m0 = blockIdx.y * 8;
    int seg = blockIdx.z;
    int j0 = seg * 128;
    const float* A0 = (pass == 0 ? g_A : g_A2) + m0 * DH;
    const float* Wp = g_W2 + d0;
    float acc[8][4];
#pragma unroll
    for (int i = 0; i < 8; i++) { acc[i][0]=0; acc[i][1]=0; acc[i][2]=0; acc[i][3]=0; }
#pragma unroll 4
    for (int j = j0; j < j0 + 128; j++) {
        float4 w = *reinterpret_cast<const float4*>(Wp + j * DM);
#pragma unroll
        for (int i = 0; i < 8; i++) {
            float a = A0[i * DH + j];
            acc[i][0] += a * w.x; acc[i][1] += a * w.y;
            acc[i][2] += a * w.z; acc[i][3] += a * w.w;
        }
    }
    float* P = g_ppart + (seg * CHUNK + m0) * DM + d0;
#pragma unroll
    for (int i = 0; i < 8; i++)
        *reinterpret_cast<float4*>(P + i * DM) = make_float4(acc[i][0], acc[i][1], acc[i][2], acc[i][3]);
}

// ---------------- reduce pred partials: mode0 -> dpred, mode1 -> write Y to out ----------------
__global__ void reduce2_kernel(int c, int mode, float* __restrict__ out) {
    int idx = blockIdx.x * 256 + threadIdx.x;   // 64*3136 = 200704 exact (784 blocks)
    int d = idx % DM;
    float s = g_b2[d];
#pragma unroll
    for (int sg = 0; sg < 4; sg++) s += g_ppart[sg * (CHUNK * DM) + idx];
    if (mode == 0)
        g_dpred[idx] = 2.0f * (s - g_nv[c * (CHUNK * DM) + idx]);
    else
        out[c * (CHUNK * DM) + idx] = s;
}

// ---------------- dh[m,j] = (sum_d dpred[m,d]*W2[j,d]) * dgelu(H[m,j]) ----------------
// warp-dot: warp handles one j and 8 m's; lanes over float4 d.
__global__ void dadh_kernel() {
    int w = (blockIdx.x * blockDim.x + threadIdx.x) >> 5;   // 4096 warps
    int lane = threadIdx.x & 31;
    int j = w >> 3;
    int m0 = (w & 7) * 8;
    const float* Wp = g_W2 + j * DM;
    float acc[8] = {0, 0, 0, 0, 0, 0, 0, 0};
    for (int d4 = lane; d4 < 784; d4 += 32) {
        float4 wv = *reinterpret_cast<const float4*>(Wp + d4 * 4);
#pragma unroll
        for (int i = 0; i < 8; i++) {
            float4 p = *reinterpret_cast<const float4*>(g_dpred + (m0 + i) * DM + d4 * 4);
            acc[i] += p.x * wv.x + p.y * wv.y + p.z * wv.z + p.w * wv.w;
        }
    }
#pragma unroll
    for (int i = 0; i < 8; i++)
#pragma unroll
        for (int o = 16; o; o >>= 1) acc[i] += __shfl_xor_sync(0xffffffffu, acc[i], o);
    if (lane == 0) {
#pragma unroll
        for (int i = 0; i < 8; i++) {
            int m = m0 + i;
            g_dh[m * DH + j] = acc[i] * dgelu_f(g_H[m * DH + j]);
        }
    }
}

// ---------------- W2[j,d] -= w * sum_m A[m,j]*dpred[m,d]  (8 j x 4 d tiles) ----------------
__global__ void updW2_kernel(float wgt) {
    int d4 = blockIdx.x * 64 + threadIdx.x;
    if (d4 >= 784) return;
    int d0 = d4 * 4;
    int j0 = blockIdx.y * 8;
    float acc[8][4];
#pragma unroll
    for (int i = 0; i < 8; i++) { acc[i][0]=0; acc[i][1]=0; acc[i][2]=0; acc[i][3]=0; }
#pragma unroll 2
    for (int m = 0; m < CHUNK; m++) {
        float4 p = *reinterpret_cast<const float4*>(g_dpred + m * DM + d0);
        const float* Am = g_A + m * DH + j0;
#pragma unroll
        for (int i = 0; i < 8; i++) {
            float a = Am[i];
            acc[i][0] += a * p.x; acc[i][1] += a * p.y;
            acc[i][2] += a * p.z; acc[i][3] += a * p.w;
        }
    }
#pragma unroll
    for (int i = 0; i < 8; i++) {
        float* Wp = g_W2 + (j0 + i) * DM + d0;
        float4 old = *reinterpret_cast<float4*>(Wp);
        old.x -= wgt * acc[i][0]; old.y -= wgt * acc[i][1];
        old.z -= wgt * acc[i][2]; old.w -= wgt * acc[i][3];
        *reinterpret_cast<float4*>(Wp) = old;
    }
}

// ---------------- W1[d,j] -= w * sum_m K[m,d]*dh[m,j]  (8 d x 4 j tiles) ----------------
__global__ void updW1_kernel(int c, float wgt) {
    int j4 = blockIdx.x * 64 + threadIdx.x;
    if (j4 >= 128) return;
    int j0 = j4 * 4;
    int dd0 = blockIdx.y * 8;
    const float* K = g_nk + c * (CHUNK * DM);
    float acc[8][4];
#pragma unroll
    for (int i = 0; i < 8; i++) { acc[i][0]=0; acc[i][1]=0; acc[i][2]=0; acc[i][3]=0; }
#pragma unroll 2
    for (int m = 0; m < CHUNK; m++) {
        float4 g = *reinterpret_cast<const float4*>(g_dh + m * DH + j0);
        const float* Km = K + m * DM + dd0;
#pragma unroll
        for (int i = 0; i < 8; i++) {
            float kv = Km[i];
            acc[i][0] += kv * g.x; acc[i][1] += kv * g.y;
            acc[i][2] += kv * g.z; acc[i][3] += kv * g.w;
        }
    }
#pragma unroll
    for (int i = 0; i < 8; i++) {
        float* Wp = g_W1 + (dd0 + i) * DH + j0;
        float4 old = *reinterpret_cast<float4*>(Wp);
        old.x -= wgt * acc[i][0]; old.y -= wgt * acc[i][1];
        old.z -= wgt * acc[i][2]; old.w -= wgt * acc[i][3];
        *reinterpret_cast<float4*>(Wp) = old;
    }
}

// ---------------- bias updates ----------------
__global__ void bias_kernel(float wgt) {
    int i = blockIdx.x * 256 + threadIdx.x;
    if (i < DH) {
        float s = 0.f;
#pragma unroll 4
        for (int m = 0; m < CHUNK; m++) s += g_dh[m * DH + i];
        g_b1[i] -= wgt * s;
    } else if (i < DH + DM) {
        int d = i - DH;
        float s = 0.f;
#pragma unroll 4
        for (int m = 0; m < CHUNK; m++) s += g_dpred[m * DM + d];
        g_b2[d] -= wgt * s;
    }
}

// ---------------- launch ----------------
extern "C" void kernel_launch(void* const* d_in, const int* in_sizes, int n_in,
                              void* d_out, int out_size) {
    const float* x   = (const float*)d_in[0];
    const float* ckw = (const float*)d_in[1];
    const float* ckb = (const float*)d_in[2];
    const float* cvw = (const float*)d_in[3];
    const float* cvb = (const float*)d_in[4];
    const float* rsk = (const float*)d_in[5];
    const float* rsv = (const float*)d_in[6];
    const float* W1  = (const float*)d_in[7];
    const float* b1  = (const float*)d_in[8];
    const float* W2  = (const float*)d_in[9];
    const float* b2  = (const float*)d_in[10];
    float* out = (float*)d_out;

    float wgt = (float)(0.1 * pow(0.9, 63.0));   // weights[i] is constant: eta0 * alpha^(CHUNK-1)

    conv_rms_kernel<<<(T_TOK * HH * WW + 255) / 256, 256>>>(x, ckw, ckb, cvw, cvb, rsk, rsv);
    init_kernel<<<512, 256>>>(W1, b1, W2, b2);

    for (int c = 0; c < NCHUNK; c++) {
        // forward with current params
        fwd_split_kernel<<<dim3(8, 4, 16), dim3(16, 4)>>>(c);
        reduce1_kernel<<<128, 256>>>(0);
        pred_split_kernel<<<dim3(13, 8, 4), 64>>>(0);
        reduce2_kernel<<<784, 256>>>(c, 0, out);
        // backward
        dadh_kernel<<<512, 256>>>();
        // parameter updates (use old A / dpred; W2 already consumed by dadh)
        updW2_kernel<<<dim3(13, 64), 64>>>(wgt);
        updW1_kernel<<<dim3(2, 392), 64>>>(c, wgt);
        bias_kernel<<<15, 256>>>(wgt);
        // recall with updated params
        fwd_split_kernel<<<dim3(8, 4, 16), dim3(16, 4)>>>(c);
        reduce1_kernel<<<128, 256>>>(1);
        pred_split_kernel<<<dim3(13, 8, 4), 64>>>(1);
        reduce2_kernel<<<784, 256>>>(c, 1, out);
    }
}

// round 3
// speedup vs baseline: 1.6252x; 1.6252x over previous
#include <cuda_runtime.h>
#include <math.h>

#define T_TOK 512
#define CHUNK 64
#define NCHUNK 8
#define HH 28
#define WW 28
#define CC 4
#define DM 3136
#define DH 512

#define FSEG 98        // fwd split-K segments (3136/98 = 32 k each)
#define PSEG 16        // pred split-K segments (512/16 = 32 k each)

// ---------------- device scratch (no allocation allowed) ----------------
__device__ __align__(16) float g_nk[T_TOK * DM];
__device__ __align__(16) float g_nv[T_TOK * DM];
__device__ __align__(16) float g_W1[DM * DH];
__device__ __align__(16) float g_W2[DH * DM];
__device__ __align__(16) float g_b1[DH];
__device__ __align__(16) float g_b2[DM];
__device__ __align__(16) float g_H[CHUNK * DH];
__device__ __align__(16) float g_A[CHUNK * DH];
__device__ __align__(16) float g_A2[CHUNK * DH];
__device__ __align__(16) float g_dpred[CHUNK * DM];
__device__ __align__(16) float g_dh[CHUNK * DH];
__device__ __align__(16) float g_fpart[FSEG * CHUNK * DH];   // 12.8 MB fwd partials
__device__ __align__(16) float g_ppart[PSEG * CHUNK * DM];   // 12.8 MB pred partials

// ---------------- math helpers ----------------
__device__ __forceinline__ float gelu_f(float x) {
    const float c = 0.7978845608028654f, a = 0.044715f;
    float u = c * (x + a * x * x * x);
    return 0.5f * x * (1.0f + tanhf(u));
}
__device__ __forceinline__ float dgelu_f(float x) {
    const float c = 0.7978845608028654f, a = 0.044715f;
    float x2 = x * x;
    float u = c * (x + a * x * x2);
    float th = tanhf(u);
    return 0.5f * (1.0f + th) + 0.5f * x * (1.0f - th * th) * c * (1.0f + 3.0f * a * x2);
}

// ---------------- conv3x3 (k & v) + rmsnorm ----------------
__global__ void conv_rms_kernel(const float* __restrict__ x,
                                const float* __restrict__ wk, const float* __restrict__ bk,
                                const float* __restrict__ wv, const float* __restrict__ bv,
                                const float* __restrict__ sk, const float* __restrict__ sv) {
    __shared__ float swk[144], swv[144], sbk[4], sbv[4], ssk[4], ssv[4];
    int tid = threadIdx.x;
    if (tid < 144) { swk[tid] = wk[tid]; swv[tid] = wv[tid]; }
    if (tid < 4) { sbk[tid] = bk[tid]; sbv[tid] = bv[tid]; ssk[tid] = sk[tid]; ssv[tid] = sv[tid]; }
    __syncthreads();
    int idx = blockIdx.x * blockDim.x + tid;
    if (idx >= T_TOK * HH * WW) return;
    int w = idx % WW;
    int h = (idx / WW) % HH;
    int t = idx / (HH * WW);

    float acck[4], accv[4];
#pragma unroll
    for (int o = 0; o < 4; o++) { acck[o] = sbk[o]; accv[o] = sbv[o]; }

    const float* xt = x + t * (CC * HH * WW);
#pragma unroll
    for (int kh = 0; kh < 3; kh++) {
        int hy = h + kh - 1;
        if (hy < 0 || hy >= HH) continue;
#pragma unroll
        for (int kw = 0; kw < 3; kw++) {
            int wx = w + kw - 1;
            if (wx < 0 || wx >= WW) continue;
            int wbase = (kh * 3 + kw) * 16;
#pragma unroll
            for (int ci = 0; ci < 4; ci++) {
                float xv = xt[ci * (HH * WW) + hy * WW + wx];
                const float* wkp = &swk[wbase + ci * 4];
                const float* wvp = &swv[wbase + ci * 4];
#pragma unroll
                for (int o = 0; o < 4; o++) { acck[o] += xv * wkp[o]; accv[o] += xv * wvp[o]; }
            }
        }
    }
    float msk = 0.f, msv = 0.f;
#pragma unroll
    for (int o = 0; o < 4; o++) { msk += acck[o] * acck[o]; msv += accv[o] * accv[o]; }
    float ik = rsqrtf(msk * 0.25f + 1e-6f);
    float iv = rsqrtf(msv * 0.25f + 1e-6f);
    int base = t * DM + (h * WW + w) * CC;
#pragma unroll
    for (int o = 0; o < 4; o++) {
        g_nk[base + o] = acck[o] * ik * ssk[o];
        g_nv[base + o] = accv[o] * iv * ssv[o];
    }
}

// ---------------- copy initial params into scratch ----------------
__global__ void init_kernel(const float* __restrict__ W1, const float* __restrict__ b1,
                            const float* __restrict__ W2, const float* __restrict__ b2) {
    int i = blockIdx.x * blockDim.x + threadIdx.x;
    int stride = gridDim.x * blockDim.x;
    for (int k = i; k < DM * DH; k += stride) { g_W1[k] = W1[k]; g_W2[k] = W2[k]; }
    if (i < DH) g_b1[i] = b1[i];
    if (i < DM) g_b2[i] = b2[i];
}

// ---------------- fwd split-K GEMM: partial[seg][m][n] = sum_{k in seg} K[m,k]*W1[k,n]
// thread tile: 4m x 8n, 32 k per seg. 392 blocks x 256 thr = 100352 threads.
__global__ void fwd_gemm_kernel(int c) {
    int f = blockIdx.x * 256 + threadIdx.x;
    int n0 = (f & 63) * 8;            // 64 n-tiles of 8
    int m0 = ((f >> 6) & 15) * 4;     // 16 m-tiles of 4
    int seg = f >> 10;                // 0..97
    int k0 = seg * 32;
    const float* K = g_nk + (c * CHUNK + m0) * DM;
    const float* Wp = g_W1 + n0;
    float acc[4][8];
#pragma unroll
    for (int i = 0; i < 4; i++)
#pragma unroll
        for (int j = 0; j < 8; j++) acc[i][j] = 0.f;

#pragma unroll 8
    for (int k = k0; k < k0 + 32; k++) {
        float4 wa = *reinterpret_cast<const float4*>(Wp + k * DH);
        float4 wb = *reinterpret_cast<const float4*>(Wp + k * DH + 4);
        float wv[8] = {wa.x, wa.y, wa.z, wa.w, wb.x, wb.y, wb.z, wb.w};
        float x[4] = {K[k], K[DM + k], K[2 * DM + k], K[3 * DM + k]};
#pragma unroll
        for (int i = 0; i < 4; i++)
#pragma unroll
            for (int j = 0; j < 8; j++) acc[i][j] += x[i] * wv[j];
    }
    float* P = g_fpart + seg * (CHUNK * DH) + m0 * DH + n0;
#pragma unroll
    for (int i = 0; i < 4; i++) {
        *reinterpret_cast<float4*>(P + i * DH)     = make_float4(acc[i][0], acc[i][1], acc[i][2], acc[i][3]);
        *reinterpret_cast<float4*>(P + i * DH + 4) = make_float4(acc[i][4], acc[i][5], acc[i][6], acc[i][7]);
    }
}

// ---------------- reduce fwd partials -> H, A (pass selects A vs A2) ----------------
__global__ void reduce1_kernel(int pass) {
    int idx = blockIdx.x * 256 + threadIdx.x;   // 64*512 = 32768 exact (128 blocks)
    float s = g_b1[idx & (DH - 1)];
#pragma unroll 14
    for (int sg = 0; sg < FSEG; sg++) s += g_fpart[sg * (CHUNK * DH) + idx];
    g_H[idx] = s;
    float a = gelu_f(s);
    if (pass == 0) g_A[idx] = a; else g_A2[idx] = a;
}

// ---------------- pred split-K GEMM: partial[seg][m][d] = sum_{j in seg} A[m,j]*W2[j,d]
// thread tile: 4m x 8d, 32 j per seg. 392 blocks x 256 thr = 100352 threads.
__global__ void pred_gemm_kernel(int pass) {
    int f = blockIdx.x * 256 + threadIdx.x;
    int dt = f % 392;                  // 392 d-tiles of 8
    int d0 = dt * 8;
    int m0 = ((f / 392) & 15) * 4;     // 16 m-tiles of 4
    int seg = f / 6272;                // 0..15
    int j0 = seg * 32;
    const float* A0 = (pass == 0 ? g_A : g_A2) + m0 * DH;
    const float* Wp = g_W2 + d0;
    float acc[4][8];
#pragma unroll
    for (int i = 0; i < 4; i++)
#pragma unroll
        for (int j = 0; j < 8; j++) acc[i][j] = 0.f;

#pragma unroll 8
    for (int j = j0; j < j0 + 32; j++) {
        float4 wa = *reinterpret_cast<const float4*>(Wp + j * DM);
        float4 wb = *reinterpret_cast<const float4*>(Wp + j * DM + 4);
        float wv[8] = {wa.x, wa.y, wa.z, wa.w, wb.x, wb.y, wb.z, wb.w};
        float a0 = A0[j], a1 = A0[DH + j], a2 = A0[2 * DH + j], a3 = A0[3 * DH + j];
        float av[4] = {a0, a1, a2, a3};
#pragma unroll
        for (int i = 0; i < 4; i++)
#pragma unroll
            for (int jj = 0; jj < 8; jj++) acc[i][jj] += av[i] * wv[jj];
    }
    float* P = g_ppart + seg * (CHUNK * DM) + m0 * DM + d0;
#pragma unroll
    for (int i = 0; i < 4; i++) {
        *reinterpret_cast<float4*>(P + i * DM)     = make_float4(acc[i][0], acc[i][1], acc[i][2], acc[i][3]);
        *reinterpret_cast<float4*>(P + i * DM + 4) = make_float4(acc[i][4], acc[i][5], acc[i][6], acc[i][7]);
    }
}

// ---------------- reduce pred partials: mode0 -> dpred, mode1 -> write Y to out ----------------
__global__ void reduce2_kernel(int c, int mode, float* __restrict__ out) {
    int idx = blockIdx.x * 256 + threadIdx.x;   // 64*3136 = 200704 exact (784 blocks)
    int d = idx % DM;
    float s = g_b2[d];
#pragma unroll
    for (int sg = 0; sg < PSEG; sg++) s += g_ppart[sg * (CHUNK * DM) + idx];
    if (mode == 0)
        g_dpred[idx] = 2.0f * (s - g_nv[c * (CHUNK * DM) + idx]);
    else
        out[c * (CHUNK * DM) + idx] = s;
}

// ---------------- dh[m,j] = (sum_d dpred[m,d]*W2[j,d]) * dgelu(H[m,j]) ----------------
// warp-dot: warp handles one j and 8 m's; lanes over float4 d. 4096 warps.
__global__ void dadh_kernel() {
    int w = (blockIdx.x * blockDim.x + threadIdx.x) >> 5;
    int lane = threadIdx.x & 31;
    int j = w >> 3;
    int m0 = (w & 7) * 8;
    const float* Wp = g_W2 + j * DM;
    float acc[8] = {0, 0, 0, 0, 0, 0, 0, 0};
    for (int d4 = lane; d4 < 784; d4 += 32) {
        float4 wv = *reinterpret_cast<const float4*>(Wp + d4 * 4);
#pragma unroll
        for (int i = 0; i < 8; i++) {
            float4 p = *reinterpret_cast<const float4*>(g_dpred + (m0 + i) * DM + d4 * 4);
            acc[i] += p.x * wv.x + p.y * wv.y + p.z * wv.z + p.w * wv.w;
        }
    }
#pragma unroll
    for (int i = 0; i < 8; i++)
#pragma unroll
        for (int o = 16; o; o >>= 1) acc[i] += __shfl_xor_sync(0xffffffffu, acc[i], o);
    if (lane == 0) {
#pragma unroll
        for (int i = 0; i < 8; i++) {
            int m = m0 + i;
            g_dh[m * DH + j] = acc[i] * dgelu_f(g_H[m * DH + j]);
        }
    }
}

// ---------------- fused parameter update: W2, W1, b1, b2 in one kernel ----------------
// region A (50176 thr): W2[j,d] -= w * sum_m A[m,j]*dpred[m,d]   (8j x 4d tiles)
// region B (50176 thr): W1[d,j] -= w * sum_m K[m,d]*dh[m,j]      (8d x 4j tiles)
// region C (3648 thr):  biases
__global__ void update_kernel(int c, float wgt) {
    int f = blockIdx.x * 256 + threadIdx.x;
    if (f < 50176) {
        int d4 = f % 784;
        int d0 = d4 * 4;
        int j0 = (f / 784) * 8;
        float acc[8][4];
#pragma unroll
        for (int i = 0; i < 8; i++) { acc[i][0]=0; acc[i][1]=0; acc[i][2]=0; acc[i][3]=0; }
#pragma unroll 4
        for (int m = 0; m < CHUNK; m++) {
            float4 p = *reinterpret_cast<const float4*>(g_dpred + m * DM + d0);
            const float* Am = g_A + m * DH + j0;
#pragma unroll
            for (int i = 0; i < 8; i++) {
                float a = Am[i];
                acc[i][0] += a * p.x; acc[i][1] += a * p.y;
                acc[i][2] += a * p.z; acc[i][3] += a * p.w;
            }
        }
#pragma unroll
        for (int i = 0; i < 8; i++) {
            float* Wp = g_W2 + (j0 + i) * DM + d0;
            float4 old = *reinterpret_cast<float4*>(Wp);
            old.x -= wgt * acc[i][0]; old.y -= wgt * acc[i][1];
            old.z -= wgt * acc[i][2]; old.w -= wgt * acc[i][3];
            *reinterpret_cast<float4*>(Wp) = old;
        }
    } else if (f < 100352) {
        int g = f - 50176;
        int j4 = g % 128;
        int j0 = j4 * 4;
        int dd0 = (g / 128) * 8;
        const float* K = g_nk + c * (CHUNK * DM);
        float acc[8][4];
#pragma unroll
        for (int i = 0; i < 8; i++) { acc[i][0]=0; acc[i][1]=0; acc[i][2]=0; acc[i][3]=0; }
#pragma unroll 4
        for (int m = 0; m < CHUNK; m++) {
            float4 gg = *reinterpret_cast<const float4*>(g_dh + m * DH + j0);
            const float* Km = K + m * DM + dd0;
#pragma unroll
            for (int i = 0; i < 8; i++) {
                float kv = Km[i];
                acc[i][0] += kv * gg.x; acc[i][1] += kv * gg.y;
                acc[i][2] += kv * gg.z; acc[i][3] += kv * gg.w;
            }
        }
#pragma unroll
        for (int i = 0; i < 8; i++) {
            float* Wp = g_W1 + (dd0 + i) * DH + j0;
            float4 old = *reinterpret_cast<float4*>(Wp);
            old.x -= wgt * acc[i][0]; old.y -= wgt * acc[i][1];
            old.z -= wgt * acc[i][2]; old.w -= wgt * acc[i][3];
            *reinterpret_cast<float4*>(Wp) = old;
        }
    } else {
        int i = f - 100352;
        if (i < DH) {
            float s = 0.f;
#pragma unroll 8
            for (int m = 0; m < CHUNK; m++) s += g_dh[m * DH + i];
            g_b1[i] -= wgt * s;
        } else if (i < DH + DM) {
            int d = i - DH;
            float s = 0.f;
#pragma unroll 8
            for (int m = 0; m < CHUNK; m++) s += g_dpred[m * DM + d];
            g_b2[d] -= wgt * s;
        }
    }
}

// ---------------- launch ----------------
extern "C" void kernel_launch(void* const* d_in, const int* in_sizes, int n_in,
                              void* d_out, int out_size) {
    const float* x   = (const float*)d_in[0];
    const float* ckw = (const float*)d_in[1];
    const float* ckb = (const float*)d_in[2];
    const float* cvw = (const float*)d_in[3];
    const float* cvb = (const float*)d_in[4];
    const float* rsk = (const float*)d_in[5];
    const float* rsv = (const float*)d_in[6];
    const float* W1  = (const float*)d_in[7];
    const float* b1  = (const float*)d_in[8];
    const float* W2  = (const float*)d_in[9];
    const float* b2  = (const float*)d_in[10];
    float* out = (float*)d_out;

    // weights[i] = eta0*0.9^i * 0.9^63/0.9^i = const
    float wgt = (float)(0.1 * pow(0.9, 63.0));

    conv_rms_kernel<<<(T_TOK * HH * WW + 255) / 256, 256>>>(x, ckw, ckb, cvw, cvb, rsk, rsv);
    init_kernel<<<512, 256>>>(W1, b1, W2, b2);

    for (int c = 0; c < NCHUNK; c++) {
        // forward with current params
        fwd_gemm_kernel<<<392, 256>>>(c);
        reduce1_kernel<<<128, 256>>>(0);
        pred_gemm_kernel<<<392, 256>>>(0);
        reduce2_kernel<<<784, 256>>>(c, 0, out);
        // backward + fused update
        dadh_kernel<<<512, 256>>>();
        update_kernel<<<407, 256>>>(c, wgt);
        // recall with updated params
        fwd_gemm_kernel<<<392, 256>>>(c);
        reduce1_kernel<<<128, 256>>>(1);
        pred_gemm_kernel<<<392, 256>>>(1);
        reduce2_kernel<<<784, 256>>>(c, 1, out);
    }
}